// round 3
// baseline (speedup 1.0000x reference)
#include <cuda_runtime.h>
#include <math.h>

#define NB 8
#define NC 16
#define ND 64
#define NH 64
#define NW 64
#define NR 32
#define NBC 128          // B*C
#define NCHUNK 16        // d-chunks per bc (4 d-slices each)
#define EPSV 1e-5f

// ---------------------------------------------------------------------------
// Per-block partial sums (no atomics, no zeroing: fully overwritten each call)
// ---------------------------------------------------------------------------
__device__ float g_P1[NBC * ND];              // [bc][d]            (d disjoint per chunk)
__device__ float g_P2[NBC * NCHUNK * NH];     // [bc][chunk][h]
__device__ float g_P3[NBC * NCHUNK * NW];     // [bc][chunk][w]
__device__ float g_PQ[NBC * NCHUNK];          // [bc][chunk]

// ---------------------------------------------------------------------------
// Kernel 1: single streaming pass over x (134 MB). Memory-bound.
// grid = (16 chunks, 128 bc), 256 threads. Thread (r0=tid>>4, wq=tid&15):
// row r = r0 + 16*i, i in [0,16): d_local = i>>2, h = r0 + 16*(i&3), w = 4*wq+.
// All accumulation in registers; block reduce via shuffles + shared; plain
// stores of per-block partials (no global atomics).
// ---------------------------------------------------------------------------
__global__ void __launch_bounds__(256) reduce_kernel(const float* __restrict__ x) {
    const int bc    = blockIdx.y;
    const int chunk = blockIdx.x;
    const int tid   = threadIdx.x;
    const int r0 = tid >> 4;
    const int wq = tid & 15;

    const float4* xb = (const float4*)x + (size_t)bc * 65536 + (size_t)chunk * 4096;

    float aD[4] = {0.f, 0.f, 0.f, 0.f};
    float aH[4] = {0.f, 0.f, 0.f, 0.f};
    float aW[4] = {0.f, 0.f, 0.f, 0.f};
    float ssq = 0.f;

#pragma unroll
    for (int i = 0; i < 16; i++) {
        float4 v = __ldcs(&xb[(r0 + 16 * i) * 16 + wq]);
        float s = (v.x + v.y) + (v.z + v.w);
        aD[i >> 2] += s;
        aH[i & 3]  += s;
        aW[0] += v.x; aW[1] += v.y; aW[2] += v.z; aW[3] += v.w;
        ssq = fmaf(v.x, v.x, ssq);
        ssq = fmaf(v.y, v.y, ssq);
        ssq = fmaf(v.z, v.z, ssq);
        ssq = fmaf(v.w, v.w, ssq);
    }

    __shared__ float s1[4];
    __shared__ float s2[64];
    __shared__ float s3[64];
    __shared__ float sq;
    if (tid < 64) { s2[tid] = 0.f; s3[tid] = 0.f; }
    if (tid < 4)  s1[tid] = 0.f;
    if (tid == 0) sq = 0.f;
    __syncthreads();

    const unsigned FULL = 0xffffffffu;
    const int lane = tid & 31;

    // aD + ssq: full-warp trees (identical d semantics across lanes)
#pragma unroll
    for (int k = 0; k < 4; k++) {
        float v = aD[k];
        v += __shfl_xor_sync(FULL, v, 16);
        v += __shfl_xor_sync(FULL, v, 8);
        v += __shfl_xor_sync(FULL, v, 4);
        v += __shfl_xor_sync(FULL, v, 2);
        v += __shfl_xor_sync(FULL, v, 1);
        if (lane == 0) atomicAdd(&s1[k], v);
    }
    {
        float v = ssq;
        v += __shfl_xor_sync(FULL, v, 16);
        v += __shfl_xor_sync(FULL, v, 8);
        v += __shfl_xor_sync(FULL, v, 4);
        v += __shfl_xor_sync(FULL, v, 2);
        v += __shfl_xor_sync(FULL, v, 1);
        if (lane == 0) atomicAdd(&sq, v);
    }
    // aH: same h within each 16-lane half-warp
    const int h0 = tid >> 4;
#pragma unroll
    for (int k = 0; k < 4; k++) {
        float v = aH[k];
        v += __shfl_xor_sync(FULL, v, 8);
        v += __shfl_xor_sync(FULL, v, 4);
        v += __shfl_xor_sync(FULL, v, 2);
        v += __shfl_xor_sync(FULL, v, 1);
        if ((lane & 15) == 0) atomicAdd(&s2[h0 + 16 * k], v);
    }
    // aW: lanes l and l^16 share the same w-group
#pragma unroll
    for (int k = 0; k < 4; k++) {
        float v = aW[k];
        v += __shfl_xor_sync(FULL, v, 16);
        if (lane < 16) atomicAdd(&s3[wq * 4 + k], v);
    }
    __syncthreads();

    // Plain stores into this block's private slots
    if (tid < 4)
        g_P1[bc * 64 + chunk * 4 + tid] = s1[tid];
    if (tid < 64) {
        g_P2[(bc * NCHUNK + chunk) * 64 + tid] = s2[tid];
        g_P3[(bc * NCHUNK + chunk) * 64 + tid] = s3[tid];
    }
    if (tid == 0)
        g_PQ[bc * NCHUNK + chunk] = sq;
}

// ---------------------------------------------------------------------------
// Kernel 2: reduce partials -> BN stats -> three 64x32 projections -> GELU.
// One block per bc, 96 threads (one per output element).
// ---------------------------------------------------------------------------
__global__ void __launch_bounds__(96) finalize_kernel(
    const float* __restrict__ gamma, const float* __restrict__ beta,
    const float* __restrict__ core1, const float* __restrict__ core2,
    const float* __restrict__ core3, float* __restrict__ out) {
    const int bc = blockIdx.x;
    const int c  = bc & 15;
    const int b  = bc >> 4;
    const int t  = threadIdx.x;   // 0..95

    __shared__ float sv[192];     // v1[0:64], v2[64:128], v3[128:192]
    __shared__ float rsum[96], rsq[96];
    __shared__ float s_scale, s_shift;

    // Per-bc axis vectors from partials
    if (t < 64) {
        float a2 = 0.f, a3 = 0.f;
#pragma unroll
        for (int ch = 0; ch < NCHUNK; ch++) {
            a2 += g_P2[(bc * NCHUNK + ch) * 64 + t];
            a3 += g_P3[(bc * NCHUNK + ch) * 64 + t];
        }
        sv[t]       = g_P1[bc * 64 + t];
        sv[64 + t]  = a2;
        sv[128 + t] = a3;
    }

    // Channel stats: sum of x over channel c (512 P1 entries) and sum of x^2
    float ls = 0.f, lq = 0.f;
    for (int i = t; i < 512; i += 96) {
        int bp = i >> 6, d = i & 63;
        ls += __ldg(&g_P1[(bp * 16 + c) * 64 + d]);
    }
    for (int i = t; i < 128; i += 96) {
        int bp = i >> 4, ch = i & 15;
        lq += __ldg(&g_PQ[(bp * 16 + c) * NCHUNK + ch]);
    }
    rsum[t] = ls; rsq[t] = lq;
    __syncthreads();

    if (t == 0) {
        float tot = 0.f, sq = 0.f;
        for (int i = 0; i < 96; i++) { tot += rsum[i]; sq += rsq[i]; }
        const float N = 2097152.0f;        // B*D*H*W
        float mean = tot / N;
        float var  = sq / N - mean * mean;
        float inv  = rsqrtf(var + EPSV);
        float sc   = gamma[c] * inv;
        s_scale = sc;
        s_shift = beta[c] - mean * sc;
    }
    __syncthreads();

    // Normalize the axis-mean vectors in place
    if (t < 64) {
        const float invHW = 1.0f / 4096.0f;
        float sc = s_scale, sh = s_shift;
        sv[t]       = sv[t]       * invHW * sc + sh;
        sv[64 + t]  = sv[64 + t]  * invHW * sc + sh;
        sv[128 + t] = sv[128 + t] * invHW * sc + sh;
    }
    __syncthreads();

    const int mode = t >> 5;   // 0: core1, 1: core2 (mean over s), 2: core3
    const int r    = t & 31;
    float acc = 0.f;
    if (mode == 0) {
#pragma unroll
        for (int d = 0; d < 64; d++) acc = fmaf(sv[d], core1[d * 32 + r], acc);
    } else if (mode == 1) {
        // W2[h][r] = mean_s core2[r][h][s], computed on the fly.
        // Thread r walks core2 row r contiguously: 64 h-groups of 32 floats.
        const float4* c2 = (const float4*)core2 + (size_t)r * 512;
        for (int h = 0; h < 64; h++) {
            float hs = 0.f;
#pragma unroll
            for (int k = 0; k < 8; k++) {
                float4 q = __ldg(&c2[h * 8 + k]);
                hs += (q.x + q.y) + (q.z + q.w);
            }
            acc = fmaf(sv[64 + h], hs, acc);
        }
        acc *= (1.0f / 32.0f);
    } else {
#pragma unroll
        for (int w = 0; w < 64; w++) acc = fmaf(sv[128 + w], core3[r * 64 + w], acc);
    }
    float g = 0.5f * acc * (1.0f + erff(acc * 0.70710678118654752f));
    out[b * 1536 + c * 96 + t] = g;
}

// ---------------------------------------------------------------------------
// kernel_launch — inputs: x, gamma, beta, core1, core2, core3
// ---------------------------------------------------------------------------
extern "C" void kernel_launch(void* const* d_in, const int* in_sizes, int n_in,
                              void* d_out, int out_size) {
    const float* x     = (const float*)d_in[0];
    const float* gamma = (const float*)d_in[1];
    const float* beta  = (const float*)d_in[2];
    const float* core1 = (const float*)d_in[3];
    const float* core2 = (const float*)d_in[4];
    const float* core3 = (const float*)d_in[5];
    float* out = (float*)d_out;

    reduce_kernel<<<dim3(NCHUNK, NBC), 256>>>(x);
    finalize_kernel<<<NBC, 96>>>(gamma, beta, core1, core2, core3, out);
}

// round 7
// speedup vs baseline: 1.7762x; 1.7762x over previous
#include <cuda_runtime.h>
#include <math.h>

#define NB 8
#define NC 16
#define ND 64
#define NH 64
#define NW 64
#define NR 32
#define NBC 128          // B*C
#define NCHUNK 16        // d-chunks per bc (4 d-slices each)
#define EPSV 1e-5f

// ---------------------------------------------------------------------------
// Per-block partial sums + W2 table (plain stores, fully overwritten each call)
// ---------------------------------------------------------------------------
__device__ float g_P1[NBC * ND];              // [bc][d]  (d disjoint per chunk)
__device__ float g_P2[NBC * NCHUNK * NH];     // [bc][chunk][h]
__device__ float g_P3[NBC * NCHUNK * NW];     // [bc][chunk][w]
__device__ float g_PQ[NBC * NCHUNK];          // [bc][chunk]
__device__ float g_W2[NH * NR];               // W2[h*32+r] = mean_s core2[r][h][s]

// ---------------------------------------------------------------------------
// Kernel 1: single pass over x (134 MB). grid = (16 chunks, 128 bc), 256 thr.
// Thread (r0=tid>>4, wq=tid&15): row r = r0 + 16*i, i in [0,16):
//   d_local = i>>2, h = r0 + 16*(i&3), w = 4*wq + component.
// Register accumulation; shuffle/shared block reduce; plain partial stores.
// Tail: the 128 chunk==15 blocks also fill the W2 table (hidden work).
// ---------------------------------------------------------------------------
__global__ void __launch_bounds__(256) reduce_kernel(const float* __restrict__ x,
                                                     const float* __restrict__ core2) {
    const int bc    = blockIdx.y;
    const int chunk = blockIdx.x;
    const int tid   = threadIdx.x;
    const int r0 = tid >> 4;
    const int wq = tid & 15;

    const float4* xb = (const float4*)x + (size_t)bc * 65536 + (size_t)chunk * 4096;

    float aD[4] = {0.f, 0.f, 0.f, 0.f};
    float aH[4] = {0.f, 0.f, 0.f, 0.f};
    float aW[4] = {0.f, 0.f, 0.f, 0.f};
    float ssq = 0.f;

#pragma unroll
    for (int i = 0; i < 16; i++) {
        float4 v = xb[(r0 + 16 * i) * 16 + wq];
        float s = (v.x + v.y) + (v.z + v.w);
        aD[i >> 2] += s;
        aH[i & 3]  += s;
        aW[0] += v.x; aW[1] += v.y; aW[2] += v.z; aW[3] += v.w;
        ssq = fmaf(v.x, v.x, ssq);
        ssq = fmaf(v.y, v.y, ssq);
        ssq = fmaf(v.z, v.z, ssq);
        ssq = fmaf(v.w, v.w, ssq);
    }

    __shared__ float s1[4];
    __shared__ float s2[64];
    __shared__ float s3[64];
    __shared__ float sq;
    if (tid < 64) { s2[tid] = 0.f; s3[tid] = 0.f; }
    if (tid < 4)  s1[tid] = 0.f;
    if (tid == 0) sq = 0.f;
    __syncthreads();

    const unsigned FULL = 0xffffffffu;
    const int lane = tid & 31;

    // aD + ssq: full-warp trees (identical d semantics across lanes)
#pragma unroll
    for (int k = 0; k < 4; k++) {
        float v = aD[k];
        v += __shfl_xor_sync(FULL, v, 16);
        v += __shfl_xor_sync(FULL, v, 8);
        v += __shfl_xor_sync(FULL, v, 4);
        v += __shfl_xor_sync(FULL, v, 2);
        v += __shfl_xor_sync(FULL, v, 1);
        if (lane == 0) atomicAdd(&s1[k], v);
    }
    {
        float v = ssq;
        v += __shfl_xor_sync(FULL, v, 16);
        v += __shfl_xor_sync(FULL, v, 8);
        v += __shfl_xor_sync(FULL, v, 4);
        v += __shfl_xor_sync(FULL, v, 2);
        v += __shfl_xor_sync(FULL, v, 1);
        if (lane == 0) atomicAdd(&sq, v);
    }
    // aH: same h within each 16-lane half-warp
    const int h0 = tid >> 4;
#pragma unroll
    for (int k = 0; k < 4; k++) {
        float v = aH[k];
        v += __shfl_xor_sync(FULL, v, 8);
        v += __shfl_xor_sync(FULL, v, 4);
        v += __shfl_xor_sync(FULL, v, 2);
        v += __shfl_xor_sync(FULL, v, 1);
        if ((lane & 15) == 0) atomicAdd(&s2[h0 + 16 * k], v);
    }
    // aW: lanes l and l^16 share the same w-group
#pragma unroll
    for (int k = 0; k < 4; k++) {
        float v = aW[k];
        v += __shfl_xor_sync(FULL, v, 16);
        if (lane < 16) atomicAdd(&s3[wq * 4 + k], v);
    }
    __syncthreads();

    // Plain stores into this block's private slots
    if (tid < 4)
        g_P1[bc * 64 + chunk * 4 + tid] = s1[tid];
    if (tid < 64) {
        g_P2[(bc * NCHUNK + chunk) * 64 + tid] = s2[tid];
        g_P3[(bc * NCHUNK + chunk) * 64 + tid] = s3[tid];
    }
    if (tid == 0)
        g_PQ[bc * NCHUNK + chunk] = sq;

    // ---- W2 table: 128 blocks (chunk==15) x 16 entries = 2048 entries -----
    // Entry te = h*32 + r ; value = mean_s core2[r][h][s].
    // 16 threads per entry, 2 floats each, 16-lane shuffle reduce.
    if (chunk == NCHUNK - 1) {
        const int e  = tid >> 4;               // 0..15 entry within block
        const int l  = tid & 15;
        const int te = bc * 16 + e;            // 0..2047
        const int h  = te >> 5, r = te & 31;
        float2 v2 = *(const float2*)(core2 + (size_t)r * 2048 + h * 32 + l * 2);
        float s = v2.x + v2.y;
        s += __shfl_xor_sync(FULL, s, 8);
        s += __shfl_xor_sync(FULL, s, 4);
        s += __shfl_xor_sync(FULL, s, 2);
        s += __shfl_xor_sync(FULL, s, 1);
        if (l == 0) g_W2[te] = s * (1.0f / 32.0f);
    }
}

// ---------------------------------------------------------------------------
// Kernel 2: reduce partials -> BN stats -> three 64x32 projections -> GELU.
// One block per bc, 128 threads.
// ---------------------------------------------------------------------------
__global__ void __launch_bounds__(128) finalize_kernel(
    const float* __restrict__ gamma, const float* __restrict__ beta,
    const float* __restrict__ core1, const float* __restrict__ core3,
    float* __restrict__ out) {
    const int bc = blockIdx.x;
    const int c  = bc & 15;
    const int b  = bc >> 4;
    const int t  = threadIdx.x;   // 0..127
    const int lane = t & 31;
    const int wid  = t >> 5;

    __shared__ float sv[192];     // v1[0:64], v2[64:128], v3[128:192]
    __shared__ float wsum[4], wsq[4];
    __shared__ float s_scale, s_shift;

    // Per-bc axis vectors from partials
    if (t < 64) {
        float a2 = 0.f, a3 = 0.f;
#pragma unroll
        for (int ch = 0; ch < NCHUNK; ch++) {
            a2 += g_P2[(bc * NCHUNK + ch) * 64 + t];
            a3 += g_P3[(bc * NCHUNK + ch) * 64 + t];
        }
        sv[t]       = g_P1[bc * 64 + t];
        sv[64 + t]  = a2;
        sv[128 + t] = a3;
    }

    // Channel stats: sum over the channel's 512 P1 entries and 128 PQ entries
    float ls = 0.f, lq = 0.f;
#pragma unroll
    for (int k = 0; k < 4; k++) {
        int i = t + k * 128;              // 0..511
        int bp = i >> 6, d = i & 63;
        ls += __ldg(&g_P1[(bp * 16 + c) * 64 + d]);
    }
    {
        int bp = t >> 4, ch = t & 15;     // 0..127
        lq += __ldg(&g_PQ[(bp * 16 + c) * NCHUNK + ch]);
    }
    const unsigned FULL = 0xffffffffu;
    ls += __shfl_xor_sync(FULL, ls, 16);
    ls += __shfl_xor_sync(FULL, ls, 8);
    ls += __shfl_xor_sync(FULL, ls, 4);
    ls += __shfl_xor_sync(FULL, ls, 2);
    ls += __shfl_xor_sync(FULL, ls, 1);
    lq += __shfl_xor_sync(FULL, lq, 16);
    lq += __shfl_xor_sync(FULL, lq, 8);
    lq += __shfl_xor_sync(FULL, lq, 4);
    lq += __shfl_xor_sync(FULL, lq, 2);
    lq += __shfl_xor_sync(FULL, lq, 1);
    if (lane == 0) { wsum[wid] = ls; wsq[wid] = lq; }
    __syncthreads();

    if (t == 0) {
        float tot = wsum[0] + wsum[1] + wsum[2] + wsum[3];
        float sq  = wsq[0] + wsq[1] + wsq[2] + wsq[3];
        const float N = 2097152.0f;        // B*D*H*W
        float mean = tot / N;
        float var  = sq / N - mean * mean;
        float inv  = rsqrtf(var + EPSV);
        float sc   = gamma[c] * inv;
        s_scale = sc;
        s_shift = beta[c] - mean * sc;
    }
    __syncthreads();

    // Normalize the axis-mean vectors in place
    if (t < 64) {
        const float invHW = 1.0f / 4096.0f;
        float sc = s_scale, sh = s_shift;
        sv[t]       = sv[t]       * invHW * sc + sh;
        sv[64 + t]  = sv[64 + t]  * invHW * sc + sh;
        sv[128 + t] = sv[128 + t] * invHW * sc + sh;
    }
    __syncthreads();

    if (t < 96) {
        const int mode = t >> 5;   // 0: core1, 1: W2 table, 2: core3
        const int r    = t & 31;
        float acc = 0.f;
        if (mode == 0) {
#pragma unroll
            for (int d = 0; d < 64; d++) acc = fmaf(sv[d], __ldg(&core1[d * 32 + r]), acc);
        } else if (mode == 1) {
#pragma unroll
            for (int h = 0; h < 64; h++) acc = fmaf(sv[64 + h], g_W2[h * 32 + r], acc);
        } else {
#pragma unroll
            for (int w = 0; w < 64; w++) acc = fmaf(sv[128 + w], __ldg(&core3[r * 64 + w]), acc);
        }
        float g = 0.5f * acc * (1.0f + erff(acc * 0.70710678118654752f));
        out[b * 1536 + c * 96 + t] = g;
    }
}

// ---------------------------------------------------------------------------
// kernel_launch — inputs: x, gamma, beta, core1, core2, core3
// ---------------------------------------------------------------------------
extern "C" void kernel_launch(void* const* d_in, const int* in_sizes, int n_in,
                              void* d_out, int out_size) {
    const float* x     = (const float*)d_in[0];
    const float* gamma = (const float*)d_in[1];
    const float* beta  = (const float*)d_in[2];
    const float* core1 = (const float*)d_in[3];
    const float* core2 = (const float*)d_in[4];
    const float* core3 = (const float*)d_in[5];
    float* out = (float*)d_out;

    reduce_kernel<<<dim3(NCHUNK, NBC), 256>>>(x, core2);
    finalize_kernel<<<NBC, 128>>>(gamma, beta, core1, core3, out);
}

// round 8
// speedup vs baseline: 1.8551x; 1.0444x over previous
#include <cuda_runtime.h>
#include <math.h>

#define NB 8
#define NC 16
#define ND 64
#define NH 64
#define NW 64
#define NR 32
#define NBC 128          // B*C
#define NCHUNK 16        // d-chunks per bc (4 d-slices each)
#define EPSV 1e-5f

// ---------------------------------------------------------------------------
// Per-block partial sums + W2 table (plain stores, fully overwritten each call)
// ---------------------------------------------------------------------------
__device__ float g_P1[NBC * ND];              // [bc][d]  (d disjoint per chunk)
__device__ float g_P2[NBC * NCHUNK * NH];     // [bc][chunk][h]
__device__ float g_P3[NBC * NCHUNK * NW];     // [bc][chunk][w]
__device__ float g_PQ[NBC * NCHUNK];          // [bc][chunk]
__device__ float g_W2[NH * NR];               // W2[h*32+r] = mean_s core2[r][h][s]

// ---------------------------------------------------------------------------
// Kernel 1: single pass over x (134 MB; __ldcs keeps it ~L2-resident across
// graph replays — MRU-like policy beats LRU's 0% hit on cyclic scans).
// grid = (16 chunks, 128 bc), 256 thr. Thread (r0=tid>>4, wq=tid&15):
// row r = r0 + 16*i, i in [0,16): d_local = i>>2, h = r0 + 16*(i&3).
// Register accumulation; shuffle/shared block reduce; plain partial stores.
// Tail: the 128 chunk==15 blocks also fill the W2 table (hidden work).
// ---------------------------------------------------------------------------
__global__ void __launch_bounds__(256) reduce_kernel(const float* __restrict__ x,
                                                     const float* __restrict__ core2) {
    const int bc    = blockIdx.y;
    const int chunk = blockIdx.x;
    const int tid   = threadIdx.x;
    const int r0 = tid >> 4;
    const int wq = tid & 15;

    const float4* xb = (const float4*)x + (size_t)bc * 65536 + (size_t)chunk * 4096;

    float aD[4] = {0.f, 0.f, 0.f, 0.f};
    float aH[4] = {0.f, 0.f, 0.f, 0.f};
    float aW[4] = {0.f, 0.f, 0.f, 0.f};
    float ssq = 0.f;

#pragma unroll
    for (int i = 0; i < 16; i++) {
        float4 v = __ldcs(&xb[(r0 + 16 * i) * 16 + wq]);
        float s = (v.x + v.y) + (v.z + v.w);
        aD[i >> 2] += s;
        aH[i & 3]  += s;
        aW[0] += v.x; aW[1] += v.y; aW[2] += v.z; aW[3] += v.w;
        ssq = fmaf(v.x, v.x, ssq);
        ssq = fmaf(v.y, v.y, ssq);
        ssq = fmaf(v.z, v.z, ssq);
        ssq = fmaf(v.w, v.w, ssq);
    }

    __shared__ float s1[4];
    __shared__ float s2[64];
    __shared__ float s3[64];
    __shared__ float sq;
    if (tid < 64) { s2[tid] = 0.f; s3[tid] = 0.f; }
    if (tid < 4)  s1[tid] = 0.f;
    if (tid == 0) sq = 0.f;
    __syncthreads();

    const unsigned FULL = 0xffffffffu;
    const int lane = tid & 31;

    // aD + ssq: full-warp trees (identical d semantics across lanes)
#pragma unroll
    for (int k = 0; k < 4; k++) {
        float v = aD[k];
        v += __shfl_xor_sync(FULL, v, 16);
        v += __shfl_xor_sync(FULL, v, 8);
        v += __shfl_xor_sync(FULL, v, 4);
        v += __shfl_xor_sync(FULL, v, 2);
        v += __shfl_xor_sync(FULL, v, 1);
        if (lane == 0) atomicAdd(&s1[k], v);
    }
    {
        float v = ssq;
        v += __shfl_xor_sync(FULL, v, 16);
        v += __shfl_xor_sync(FULL, v, 8);
        v += __shfl_xor_sync(FULL, v, 4);
        v += __shfl_xor_sync(FULL, v, 2);
        v += __shfl_xor_sync(FULL, v, 1);
        if (lane == 0) atomicAdd(&sq, v);
    }
    // aH: same h within each 16-lane half-warp
    const int h0 = tid >> 4;
#pragma unroll
    for (int k = 0; k < 4; k++) {
        float v = aH[k];
        v += __shfl_xor_sync(FULL, v, 8);
        v += __shfl_xor_sync(FULL, v, 4);
        v += __shfl_xor_sync(FULL, v, 2);
        v += __shfl_xor_sync(FULL, v, 1);
        if ((lane & 15) == 0) atomicAdd(&s2[h0 + 16 * k], v);
    }
    // aW: lanes l and l^16 share the same w-group
#pragma unroll
    for (int k = 0; k < 4; k++) {
        float v = aW[k];
        v += __shfl_xor_sync(FULL, v, 16);
        if (lane < 16) atomicAdd(&s3[wq * 4 + k], v);
    }
    __syncthreads();

    // Plain stores into this block's private slots
    if (tid < 4)
        g_P1[bc * 64 + chunk * 4 + tid] = s1[tid];
    if (tid < 64) {
        g_P2[(bc * NCHUNK + chunk) * 64 + tid] = s2[tid];
        g_P3[(bc * NCHUNK + chunk) * 64 + tid] = s3[tid];
    }
    if (tid == 0)
        g_PQ[bc * NCHUNK + chunk] = sq;

    // ---- W2 table: 128 blocks (chunk==15) x 16 entries = 2048 entries -----
    if (chunk == NCHUNK - 1) {
        const int e  = tid >> 4;               // 0..15 entry within block
        const int l  = tid & 15;
        const int te = bc * 16 + e;            // 0..2047
        const int h  = te >> 5, r = te & 31;
        float2 v2 = *(const float2*)(core2 + (size_t)r * 2048 + h * 32 + l * 2);
        float s = v2.x + v2.y;
        s += __shfl_xor_sync(FULL, s, 8);
        s += __shfl_xor_sync(FULL, s, 4);
        s += __shfl_xor_sync(FULL, s, 2);
        s += __shfl_xor_sync(FULL, s, 1);
        if (l == 0) g_W2[te] = s * (1.0f / 32.0f);
    }
}

// ---------------------------------------------------------------------------
// Kernel 2: reduce partials -> BN stats -> three 64x32 projections -> GELU.
// One block per bc, 256 threads (chunk sums split 4-way for latency hiding).
// ---------------------------------------------------------------------------
__global__ void __launch_bounds__(256) finalize_kernel(
    const float* __restrict__ gamma, const float* __restrict__ beta,
    const float* __restrict__ core1, const float* __restrict__ core3,
    float* __restrict__ out) {
    const int bc = blockIdx.x;
    const int c  = bc & 15;
    const int b  = bc >> 4;
    const int t  = threadIdx.x;   // 0..255
    const int lane = t & 31;
    const int wid  = t >> 5;

    __shared__ float sv[192];         // v1[0:64], v2[64:128], v3[128:192]
    __shared__ float part[4][64];     // chunk-split partials
    __shared__ float wsum[8], wsq[8];
    __shared__ float s_scale, s_shift;

    // Phase A: chunk sums, split across 4 groups of 64 threads.
    // group 0/1: a2 low/high chunks; group 2/3: a3 low/high chunks.
    {
        const int grp = t >> 6;       // 0..3
        const int pos = t & 63;
        const float* base = (grp < 2) ? g_P2 : g_P3;
        const int ch0 = (grp & 1) * 8;
        float a = 0.f;
#pragma unroll
        for (int ch = 0; ch < 8; ch++)
            a += base[(bc * NCHUNK + ch0 + ch) * 64 + pos];
        part[grp][pos] = a;
    }
    if (t < 64) sv[t] = g_P1[bc * 64 + t];

    // Phase B: channel stats (512 P1 entries, 128 PQ entries), 8-warp reduce.
    float ls = 0.f, lq = 0.f;
#pragma unroll
    for (int k = 0; k < 2; k++) {
        int i = t + k * 256;              // 0..511
        int bp = i >> 6, d = i & 63;
        ls += __ldg(&g_P1[(bp * 16 + c) * 64 + d]);
    }
    if (t < 128) {
        int bp = t >> 4, ch = t & 15;     // 0..127
        lq += __ldg(&g_PQ[(bp * 16 + c) * NCHUNK + ch]);
    }
    const unsigned FULL = 0xffffffffu;
    ls += __shfl_xor_sync(FULL, ls, 16);
    ls += __shfl_xor_sync(FULL, ls, 8);
    ls += __shfl_xor_sync(FULL, ls, 4);
    ls += __shfl_xor_sync(FULL, ls, 2);
    ls += __shfl_xor_sync(FULL, ls, 1);
    lq += __shfl_xor_sync(FULL, lq, 16);
    lq += __shfl_xor_sync(FULL, lq, 8);
    lq += __shfl_xor_sync(FULL, lq, 4);
    lq += __shfl_xor_sync(FULL, lq, 2);
    lq += __shfl_xor_sync(FULL, lq, 1);
    if (lane == 0) { wsum[wid] = ls; wsq[wid] = lq; }
    __syncthreads();

    if (t == 0) {
        float tot = 0.f, sq = 0.f;
#pragma unroll
        for (int i = 0; i < 8; i++) { tot += wsum[i]; sq += wsq[i]; }
        const float N = 2097152.0f;        // B*D*H*W
        float mean = tot / N;
        float var  = sq / N - mean * mean;
        float inv  = rsqrtf(var + EPSV);
        float sc   = gamma[c] * inv;
        s_scale = sc;
        s_shift = beta[c] - mean * sc;
    }
    __syncthreads();

    // Combine chunk-split partials + normalize the axis-mean vectors
    if (t < 64) {
        const float invHW = 1.0f / 4096.0f;
        float sc = s_scale, sh = s_shift;
        sv[t]       = sv[t]                     * invHW * sc + sh;
        sv[64 + t]  = (part[0][t] + part[1][t]) * invHW * sc + sh;
        sv[128 + t] = (part[2][t] + part[3][t]) * invHW * sc + sh;
    }
    __syncthreads();

    if (t < 96) {
        const int mode = t >> 5;   // 0: core1, 1: W2 table, 2: core3
        const int r    = t & 31;
        float acc = 0.f;
        if (mode == 0) {
#pragma unroll
            for (int d = 0; d < 64; d++) acc = fmaf(sv[d], __ldg(&core1[d * 32 + r]), acc);
        } else if (mode == 1) {
#pragma unroll
            for (int h = 0; h < 64; h++) acc = fmaf(sv[64 + h], g_W2[h * 32 + r], acc);
        } else {
#pragma unroll
            for (int w = 0; w < 64; w++) acc = fmaf(sv[128 + w], __ldg(&core3[r * 64 + w]), acc);
        }
        float g = 0.5f * acc * (1.0f + erff(acc * 0.70710678118654752f));
        out[b * 1536 + c * 96 + t] = g;
    }
}

// ---------------------------------------------------------------------------
// kernel_launch — inputs: x, gamma, beta, core1, core2, core3
// ---------------------------------------------------------------------------
extern "C" void kernel_launch(void* const* d_in, const int* in_sizes, int n_in,
                              void* d_out, int out_size) {
    const float* x     = (const float*)d_in[0];
    const float* gamma = (const float*)d_in[1];
    const float* beta  = (const float*)d_in[2];
    const float* core1 = (const float*)d_in[3];
    const float* core2 = (const float*)d_in[4];
    const float* core3 = (const float*)d_in[5];
    float* out = (float*)d_out;

    reduce_kernel<<<dim3(NCHUNK, NBC), 256>>>(x, core2);
    finalize_kernel<<<NBC, 256>>>(gamma, beta, core1, core3, out);
}

// round 10
// speedup vs baseline: 2.0098x; 1.0834x over previous
#include <cuda_runtime.h>
#include <math.h>

#define NBC 128          // B*C
#define EPSV 1e-5f

// ---------------------------------------------------------------------------
// Scratch (plain stores, fully overwritten each launch) + barrier state
// ---------------------------------------------------------------------------
__device__ float g_P1[NBC * 64];        // [bc][d]
__device__ float g_P2[NBC * 2 * 64];    // [bc][half][h]
__device__ float g_P3[NBC * 2 * 64];    // [bc][half][w]
__device__ float g_PQ[NBC * 2];         // [bc][half]
__device__ float g_W2[64 * 32];         // W2[h*32+r] = mean_s core2[r][h][s]
__device__ unsigned g_count = 0;        // arrival counter (reset by releaser)
__device__ unsigned g_gen   = 0;        // monotonic generation (never reset)

// ---------------------------------------------------------------------------
// Fused persistent kernel. 256 blocks x 256 threads, 2 blocks/SM co-resident.
// Phase 1: block blk handles bc = blk>>1, half = blk&1 -> 8 chunks of 4
//          d-slices each (512 KB of x). Register accumulation; aD reduced
//          per-chunk into shared; aH/aW/ssq once per block.
// Phase 2: device-wide barrier (counter + generation; deadlock-free even at
//          1 block/SM since only blocks 0..127 wait).
// Phase 3: blocks 0..127 finalize one bc each: BN stats, 3 projections, GELU.
// ---------------------------------------------------------------------------
__global__ void __launch_bounds__(256, 2) fused_kernel(
    const float* __restrict__ x, const float* __restrict__ gamma,
    const float* __restrict__ beta, const float* __restrict__ core1,
    const float* __restrict__ core2, const float* __restrict__ core3,
    float* __restrict__ out)
{
    const int blk  = blockIdx.x;      // 0..255
    const int bc   = blk >> 1;
    const int half = blk & 1;
    const int tid  = threadIdx.x;
    const int lane = tid & 31;
    const int wid  = tid >> 5;
    const int r0   = tid >> 4;        // 0..15 (row phase)
    const int wq   = tid & 15;        // float4 column
    const unsigned FULL = 0xffffffffu;

    __shared__ unsigned s_gen0;
    __shared__ float sD[32];
    __shared__ float s2[64];
    __shared__ float s3[64];
    __shared__ float sq;

    if (tid == 0) s_gen0 = *(volatile unsigned*)&g_gen;
    if (tid < 32) sD[tid] = 0.f;
    if (tid < 64) { s2[tid] = 0.f; s3[tid] = 0.f; }
    if (tid == 1) sq = 0.f;
    __syncthreads();

    // ---- Phase 1: streaming reduction over 8 chunks ----------------------
    float aH[4] = {0.f, 0.f, 0.f, 0.f};
    float aW[4] = {0.f, 0.f, 0.f, 0.f};
    float ssq = 0.f;

    const float4* xb0 = (const float4*)x + (size_t)bc * 65536 + (size_t)half * 32768;

#pragma unroll 1
    for (int j = 0; j < 8; j++) {
        const float4* xb = xb0 + j * 4096;
        float aD[4] = {0.f, 0.f, 0.f, 0.f};
#pragma unroll
        for (int i = 0; i < 16; i++) {
            float4 v = __ldcs(&xb[(r0 + 16 * i) * 16 + wq]);
            float s = (v.x + v.y) + (v.z + v.w);
            aD[i >> 2] += s;
            aH[i & 3]  += s;
            aW[0] += v.x; aW[1] += v.y; aW[2] += v.z; aW[3] += v.w;
            ssq = fmaf(v.x, v.x, ssq);
            ssq = fmaf(v.y, v.y, ssq);
            ssq = fmaf(v.z, v.z, ssq);
            ssq = fmaf(v.w, v.w, ssq);
        }
        // fold this chunk's aD into shared (warp tree + shared atomic)
#pragma unroll
        for (int k = 0; k < 4; k++) {
            float v = aD[k];
            v += __shfl_xor_sync(FULL, v, 16);
            v += __shfl_xor_sync(FULL, v, 8);
            v += __shfl_xor_sync(FULL, v, 4);
            v += __shfl_xor_sync(FULL, v, 2);
            v += __shfl_xor_sync(FULL, v, 1);
            if (lane == 0) atomicAdd(&sD[j * 4 + k], v);
        }
    }

    // ---- block epilogue: aH / aW / ssq ------------------------------------
    {
        float v = ssq;
        v += __shfl_xor_sync(FULL, v, 16);
        v += __shfl_xor_sync(FULL, v, 8);
        v += __shfl_xor_sync(FULL, v, 4);
        v += __shfl_xor_sync(FULL, v, 2);
        v += __shfl_xor_sync(FULL, v, 1);
        if (lane == 0) atomicAdd(&sq, v);
    }
    const int h0 = tid >> 4;   // r0: h phase for this thread
#pragma unroll
    for (int k = 0; k < 4; k++) {
        float v = aH[k];
        v += __shfl_xor_sync(FULL, v, 8);
        v += __shfl_xor_sync(FULL, v, 4);
        v += __shfl_xor_sync(FULL, v, 2);
        v += __shfl_xor_sync(FULL, v, 1);
        if ((lane & 15) == 0) atomicAdd(&s2[h0 + 16 * k], v);
    }
#pragma unroll
    for (int k = 0; k < 4; k++) {
        float v = aW[k];
        v += __shfl_xor_sync(FULL, v, 16);
        if (lane < 16) atomicAdd(&s3[wq * 4 + k], v);
    }
    __syncthreads();

    // ---- store partials (plain stores, per-block private slots) -----------
    if (tid < 32) g_P1[bc * 64 + half * 32 + tid] = sD[tid];
    if (tid < 64) {
        g_P2[blk * 64 + tid] = s2[tid];
        g_P3[blk * 64 + tid] = s3[tid];
    }
    if (tid == 0) g_PQ[blk] = sq;

    // ---- W2 table: blocks 0..127, 16 entries each --------------------------
    if (blk < 128) {
        const int e  = tid >> 4;               // 0..15
        const int l  = tid & 15;
        const int te = blk * 16 + e;           // 0..2047
        const int h  = te >> 5, r = te & 31;
        float2 v2 = *(const float2*)(core2 + (size_t)r * 2048 + h * 32 + l * 2);
        float s = v2.x + v2.y;
        s += __shfl_xor_sync(FULL, s, 8);
        s += __shfl_xor_sync(FULL, s, 4);
        s += __shfl_xor_sync(FULL, s, 2);
        s += __shfl_xor_sync(FULL, s, 1);
        if (l == 0) g_W2[te] = s * (1.0f / 32.0f);
    }

    // ---- Phase 2: device-wide barrier -------------------------------------
    __threadfence();          // make this block's stores visible device-wide
    __syncthreads();
    if (tid == 0) {
        unsigned old = atomicAdd(&g_count, 1);
        if (old == 255u) {            // last arriver: reset counter, release
            g_count = 0u;
            __threadfence();
            atomicAdd(&g_gen, 1u);
        }
    }
    if (blk >= 128) return;          // non-finishers done

    if (tid == 0) {
        while (*(volatile unsigned*)&g_gen == s_gen0) { __nanosleep(64); }
    }
    __syncthreads();
    __threadfence();

    // ---- Phase 3: finalize for bc = blk ------------------------------------
    const int fc = blk & 15;         // channel
    const int fb = blk >> 4;         // batch
    __shared__ float sv[192];        // v1[0:64], v2[64:128], v3[128:192]
    __shared__ float wsum[8], wsq[8];
    __shared__ float s_scale, s_shift;

    if (tid < 64) {
        sv[tid]       = __ldcg(&g_P1[blk * 64 + tid]);
        sv[64 + tid]  = __ldcg(&g_P2[(blk * 2) * 64 + tid]) + __ldcg(&g_P2[(blk * 2 + 1) * 64 + tid]);
        sv[128 + tid] = __ldcg(&g_P3[(blk * 2) * 64 + tid]) + __ldcg(&g_P3[(blk * 2 + 1) * 64 + tid]);
    }

    // channel stats: 512 P1 entries + 16 PQ entries for channel fc
    float ls = 0.f, lq = 0.f;
#pragma unroll
    for (int k = 0; k < 2; k++) {
        int i = tid + k * 256;              // 0..511
        int bp = i >> 6, d = i & 63;
        ls += __ldcg(&g_P1[(bp * 16 + fc) * 64 + d]);
    }
    if (tid < 16)
        lq = __ldcg(&g_PQ[((tid >> 1) * 16 + fc) * 2 + (tid & 1)]);
    ls += __shfl_xor_sync(FULL, ls, 16);
    ls += __shfl_xor_sync(FULL, ls, 8);
    ls += __shfl_xor_sync(FULL, ls, 4);
    ls += __shfl_xor_sync(FULL, ls, 2);
    ls += __shfl_xor_sync(FULL, ls, 1);
    lq += __shfl_xor_sync(FULL, lq, 16);
    lq += __shfl_xor_sync(FULL, lq, 8);
    lq += __shfl_xor_sync(FULL, lq, 4);
    lq += __shfl_xor_sync(FULL, lq, 2);
    lq += __shfl_xor_sync(FULL, lq, 1);
    if (lane == 0) { wsum[wid] = ls; wsq[wid] = lq; }
    __syncthreads();

    if (tid == 0) {
        float tot = 0.f, sqs = 0.f;
#pragma unroll
        for (int i = 0; i < 8; i++) { tot += wsum[i]; sqs += wsq[i]; }
        const float N = 2097152.0f;        // B*D*H*W
        float mean = tot / N;
        float var  = sqs / N - mean * mean;
        float inv  = rsqrtf(var + EPSV);
        float sc   = gamma[fc] * inv;
        s_scale = sc;
        s_shift = beta[fc] - mean * sc;
    }
    __syncthreads();

    if (tid < 64) {
        const float invHW = 1.0f / 4096.0f;
        float sc = s_scale, sh = s_shift;
        sv[tid]       = sv[tid]       * invHW * sc + sh;
        sv[64 + tid]  = sv[64 + tid]  * invHW * sc + sh;
        sv[128 + tid] = sv[128 + tid] * invHW * sc + sh;
    }
    __syncthreads();

    if (tid < 96) {
        const int mode = tid >> 5;   // 0: core1, 1: W2 table, 2: core3
        const int r    = tid & 31;
        float acc = 0.f;
        if (mode == 0) {
#pragma unroll
            for (int d = 0; d < 64; d++) acc = fmaf(sv[d], __ldg(&core1[d * 32 + r]), acc);
        } else if (mode == 1) {
#pragma unroll
            for (int h = 0; h < 64; h++) acc = fmaf(sv[64 + h], __ldcg(&g_W2[h * 32 + r]), acc);
        } else {
#pragma unroll
            for (int w = 0; w < 64; w++) acc = fmaf(sv[128 + w], __ldg(&core3[r * 64 + w]), acc);
        }
        float g = 0.5f * acc * (1.0f + erff(acc * 0.70710678118654752f));
        out[fb * 1536 + fc * 96 + tid] = g;
    }
}

// ---------------------------------------------------------------------------
// kernel_launch — inputs: x, gamma, beta, core1, core2, core3
// ---------------------------------------------------------------------------
extern "C" void kernel_launch(void* const* d_in, const int* in_sizes, int n_in,
                              void* d_out, int out_size) {
    const float* x     = (const float*)d_in[0];
    const float* gamma = (const float*)d_in[1];
    const float* beta  = (const float*)d_in[2];
    const float* core1 = (const float*)d_in[3];
    const float* core2 = (const float*)d_in[4];
    const float* core3 = (const float*)d_in[5];
    float* out = (float*)d_out;

    fused_kernel<<<256, 256>>>(x, gamma, beta, core1, core2, core3, out);
}